// round 9
// baseline (speedup 1.0000x reference)
#include <cuda_runtime.h>
#include <math_constants.h>
#include <mma.h>

using namespace nvcuda;

#define D     128
#define NMAX  50000
#define EMAX  1600000

// ---------------- device scratch (allocation-free, static) ----------------
__device__ int g_is64;
__device__ int g_src[EMAX];
__device__ int g_dst[EMAX];
__device__ __align__(16) int g_deg[NMAX + 4];
__device__ __align__(16) int g_start[NMAX + 4];
__device__ __align__(16) int g_cursor[NMAX + 4];
__device__ int g_csr_src[EMAX];

__device__ __align__(256) float g_Q[(size_t)NMAX * D];        // [N,128]
__device__ __align__(256) float g_KV[(size_t)NMAX * 2 * D];   // [N,256]: K | V interleaved
__device__ __align__(256) float g_H[(size_t)NMAX * D];        // layer-1 output

// ---------------- CSR build ----------------
__global__ void k_init_csr(const unsigned* __restrict__ ei, int N) {
    int i = blockIdx.x * blockDim.x + threadIdx.x;
    if (i < N) g_deg[i] = 0;
    if (i == 0) {
        int is64 = 1;
        for (int j = 0; j < 64; j++)
            if (ei[2 * j + 1] != 0u) is64 = 0;
        g_is64 = is64;
    }
}

__global__ void k_convert(const void* __restrict__ ei, int E) {
    int i = blockIdx.x * blockDim.x + threadIdx.x;
    if (i >= E) return;
    int s, d;
    if (g_is64) {
        const long long* p = (const long long*)ei;
        s = (int)p[i];
        d = (int)p[(size_t)E + i];
    } else {
        const int* p = (const int*)ei;
        s = p[i];
        d = p[E + i];
    }
    g_src[i] = s;
    g_dst[i] = d;
    atomicAdd(&g_deg[d], 1);
}

__global__ void k_scan(int N) {
    __shared__ int warp_sums[32];
    __shared__ int s_carry;
    int tid = threadIdx.x, lane = tid & 31, wid = tid >> 5;
    if (tid == 0) s_carry = 0;
    __syncthreads();

    const int TILE = 4096;
    for (int base = 0; base < N; base += TILE) {
        int idx = base + tid * 4;
        int4 v = make_int4(0, 0, 0, 0);
        if (idx + 3 < N) v = *(const int4*)&g_deg[idx];
        else {
            if (idx + 0 < N) v.x = g_deg[idx + 0];
            if (idx + 1 < N) v.y = g_deg[idx + 1];
            if (idx + 2 < N) v.z = g_deg[idx + 2];
            if (idx + 3 < N) v.w = g_deg[idx + 3];
        }
        int t0 = v.x, t1 = t0 + v.y, t2 = t1 + v.z, t3 = t2 + v.w;
        int inc = t3;
#pragma unroll
        for (int o = 1; o < 32; o <<= 1) {
            int n = __shfl_up_sync(0xFFFFFFFFu, inc, o);
            if (lane >= o) inc += n;
        }
        if (lane == 31) warp_sums[wid] = inc;
        __syncthreads();
        if (wid == 0) {
            int ws = warp_sums[lane];
#pragma unroll
            for (int o = 1; o < 32; o <<= 1) {
                int n = __shfl_up_sync(0xFFFFFFFFu, ws, o);
                if (lane >= o) ws += n;
            }
            warp_sums[lane] = ws;
        }
        __syncthreads();
        int warp_off = wid ? warp_sums[wid - 1] : 0;
        int e0 = s_carry + warp_off + (inc - t3);
        int tile_total = warp_sums[31];

        if (idx + 3 < N) {
            int4 e = make_int4(e0, e0 + t0, e0 + t1, e0 + t2);
            *(int4*)&g_start[idx]  = e;
            *(int4*)&g_cursor[idx] = e;
        } else {
            if (idx + 0 < N) { g_start[idx + 0] = e0;      g_cursor[idx + 0] = e0;      }
            if (idx + 1 < N) { g_start[idx + 1] = e0 + t0; g_cursor[idx + 1] = e0 + t0; }
            if (idx + 2 < N) { g_start[idx + 2] = e0 + t1; g_cursor[idx + 2] = e0 + t1; }
            if (idx + 3 < N) { g_start[idx + 3] = e0 + t2; g_cursor[idx + 3] = e0 + t2; }
        }
        __syncthreads();
        if (tid == 0) s_carry += tile_total;
        __syncthreads();
    }
    if (tid == 0) g_start[N] = s_carry;
}

__global__ void k_scatter(int E) {
    int i = blockIdx.x * blockDim.x + threadIdx.x;
    if (i >= E) return;
    int d = g_dst[i];
    int pos = atomicAdd(&g_cursor[d], 1);
    g_csr_src[pos] = g_src[i];
}

// ---------------- 3xTF32 tensor-core QKV GEMM: C = X @ W^T + b -----------
// Block: 256 thr (8 warps), 128x128 output tile; warp = 16 rows x 128 cols.
// A (X tile) staged in smem (zero-padded), B (W) read from global (L1-hot).
// Bias pre-loaded into accumulator fragments. 3-term tf32 split ~ fp32.
#define SMEM_GEMM ((128 * 128 + 16 * 128) * 4)   // X tile + bias tile = 73728 B

__global__ void __launch_bounds__(256, 2)
k_gemm_tf32(const float* __restrict__ xin, int layer,
            const float* __restrict__ qw, const float* __restrict__ qb,
            const float* __restrict__ kw, const float* __restrict__ kb,
            const float* __restrict__ vw, const float* __restrict__ vb,
            int N) {
    extern __shared__ float smem[];
    float* sX = smem;                 // [128][128]
    float* sB = smem + 128 * 128;     // [16][128] bias replicated

    const float* X = layer ? g_H : xin;
    int wsel = blockIdx.y;
    const float* W  = (wsel == 0) ? qw : (wsel == 1) ? kw : vw;
    const float* Bb = (wsel == 0) ? qb : (wsel == 1) ? kb : vb;

    int tid = threadIdx.x;
    int wm = tid >> 5;                // warp id = warp row tile (0..7)
    int lane = tid & 31;
    int m0 = blockIdx.x * 128;

    // stage X tile (zero-pad OOB rows)
    for (int t = tid; t < 128 * 32; t += 256) {
        int r = t >> 5, c = (t & 31) << 2;
        float4 v = make_float4(0.f, 0.f, 0.f, 0.f);
        if (m0 + r < N) v = *(const float4*)(X + (size_t)(m0 + r) * D + c);
        *(float4*)(sX + r * 128 + c) = v;
    }
    // stage bias replicated across 16 rows
    for (int t = tid; t < 16 * 32; t += 256) {
        int r = t >> 5, c = (t & 31) << 2;
        *(float4*)(sB + r * 128 + c) = *(const float4*)(Bb + c);
    }
    __syncthreads();

    wmma::fragment<wmma::accumulator, 16, 16, 8, float> acc[8];
#pragma unroll
    for (int n = 0; n < 8; n++)
        wmma::load_matrix_sync(acc[n], sB + n * 16, 128, wmma::mem_row_major);

#pragma unroll 4
    for (int k0 = 0; k0 < 128; k0 += 8) {
        wmma::fragment<wmma::matrix_a, 16, 16, 8, wmma::precision::tf32, wmma::row_major> aH, aL;
        wmma::load_matrix_sync(aH, sX + wm * 16 * 128 + k0, 128);
#pragma unroll
        for (int i = 0; i < aH.num_elements; i++) {
            float x = aH.x[i];
            float h = wmma::__float_to_tf32(x);
            aL.x[i] = wmma::__float_to_tf32(x - h);
            aH.x[i] = h;
        }
#pragma unroll
        for (int n = 0; n < 8; n++) {
            // B = W^T chunk: element (k, nl) = W[(n*16+nl)*128 + k] -> col_major ld=128
            wmma::fragment<wmma::matrix_b, 16, 16, 8, wmma::precision::tf32, wmma::col_major> bH, bL;
            wmma::load_matrix_sync(bH, W + (size_t)(n * 16) * D + k0, 128);
#pragma unroll
            for (int i = 0; i < bH.num_elements; i++) {
                float x = bH.x[i];
                float h = wmma::__float_to_tf32(x);
                bL.x[i] = wmma::__float_to_tf32(x - h);
                bH.x[i] = h;
            }
            wmma::mma_sync(acc[n], aH, bH, acc[n]);
            wmma::mma_sync(acc[n], aH, bL, acc[n]);
            wmma::mma_sync(acc[n], aL, bH, acc[n]);
        }
    }

    __syncthreads();   // done reading sX (may be reused as tail scratch)

    int gr0 = m0 + wm * 16;
    float* Cbase;
    int ld;
    if (wsel == 0) { Cbase = g_Q  + (size_t)gr0 * 128;                          ld = 128; }
    else           { Cbase = g_KV + (size_t)gr0 * 256 + (wsel == 2 ? 128 : 0);  ld = 256; }

    if (gr0 + 16 <= N) {
#pragma unroll
        for (int n = 0; n < 8; n++)
            wmma::store_matrix_sync(Cbase + n * 16, acc[n], ld, wmma::mem_row_major);
    } else if (gr0 < N) {
        // partial tile (not hit for N%16==0, kept for safety): stage + guarded copy
        float* scr = sX + wm * 16 * 128;
#pragma unroll
        for (int n = 0; n < 8; n++)
            wmma::store_matrix_sync(scr + n * 16, acc[n], 128, wmma::mem_row_major);
        __syncwarp();
        int rows = N - gr0;
        for (int t = lane; t < rows * 32; t += 32) {
            int r = t >> 5, c = (t & 31) << 2;
            *(float4*)(Cbase + (size_t)r * ld + c) = *(float4*)(scr + r * 128 + c);
        }
    }
}

// ---------------- fused attention (exact R5 version — proven best) --------
__global__ void k_attn(float* __restrict__ dout, int layer, int N) {
    int gw = (blockIdx.x * blockDim.x + threadIdx.x) >> 5;
    int lane = threadIdx.x & 31;
    if (gw >= N) return;

    float* outp = layer ? dout : g_H;

    int beg = g_start[gw], end = g_start[gw + 1];
    float4 q = ((const float4*)(g_Q + (size_t)gw * D))[lane];

    float m = -CUDART_INF_F, s = 0.0f;
    float4 acc = make_float4(0.f, 0.f, 0.f, 0.f);

    float4 kf, vf;
    if (beg < end) {
        int sp = g_csr_src[beg];
        const float4* kv = (const float4*)(g_KV + (size_t)sp * 256);
        kf = kv[lane];
        vf = kv[32 + lane];
    }

    for (int e = beg; e < end; e++) {
        float4 kc = kf, vc = vf;
        if (e + 1 < end) {                      // prefetch next edge
            int sp = g_csr_src[e + 1];
            const float4* kv = (const float4*)(g_KV + (size_t)sp * 256);
            kf = kv[lane];
            vf = kv[32 + lane];
        }
        float p = kc.x * q.x + kc.y * q.y + kc.z * q.z + kc.w * q.w;
#pragma unroll
        for (int o = 16; o; o >>= 1) p += __shfl_xor_sync(0xFFFFFFFFu, p, o);
        p *= 0.08838834764831845f;              // 1/sqrt(128)

        float mn = fmaxf(m, p);
        float c  = __expf(m - mn);              // exp(-inf)=0 on first edge
        float ep = __expf(p - mn);
        s = s * c + ep;
        acc.x = acc.x * c + ep * vc.x;
        acc.y = acc.y * c + ep * vc.y;
        acc.z = acc.z * c + ep * vc.z;
        acc.w = acc.w * c + ep * vc.w;
        m = mn;
    }

    float inv = (s > 0.0f) ? 1.0f / s : 0.0f;   // deg==0 -> zeros (matches ref)
    float4 o = make_float4(acc.x * inv, acc.y * inv, acc.z * inv, acc.w * inv);
    if (!layer) {                                // ELU fused into layer-1 epilogue
        o.x = (o.x > 0.f) ? o.x : expm1f(o.x);
        o.y = (o.y > 0.f) ? o.y : expm1f(o.y);
        o.z = (o.z > 0.f) ? o.z : expm1f(o.z);
        o.w = (o.w > 0.f) ? o.w : expm1f(o.w);
    }
    ((float4*)(outp + (size_t)gw * D))[lane] = o;
}

// ---------------- launch: fork CSR build alongside GEMM-1 ----------------
extern "C" void kernel_launch(void* const* d_in, const int* in_sizes, int n_in,
                              void* d_out, int out_size) {
    const float* x   = (const float*)d_in[0];
    const void*  ei  = d_in[1];
    const float* q1w = (const float*)d_in[2];  const float* q1b = (const float*)d_in[3];
    const float* k1w = (const float*)d_in[4];  const float* k1b = (const float*)d_in[5];
    const float* v1w = (const float*)d_in[6];  const float* v1b = (const float*)d_in[7];
    const float* q2w = (const float*)d_in[8];  const float* q2b = (const float*)d_in[9];
    const float* k2w = (const float*)d_in[10]; const float* k2b = (const float*)d_in[11];
    const float* v2w = (const float*)d_in[12]; const float* v2b = (const float*)d_in[13];

    int N = in_sizes[0] / D;
    int E = in_sizes[1] / 2;
    float* out = (float*)d_out;

    cudaFuncSetAttribute(k_gemm_tf32, cudaFuncAttributeMaxDynamicSharedMemorySize, SMEM_GEMM);

    int eb = (E + 255) / 256;
    int nb = (N + 255) / 256;

    cudaStream_t s2;
    cudaEvent_t evFork, evJoin;
    cudaStreamCreateWithFlags(&s2, cudaStreamNonBlocking);
    cudaEventCreateWithFlags(&evFork, cudaEventDisableTiming);
    cudaEventCreateWithFlags(&evJoin, cudaEventDisableTiming);

    // fork: CSR build on s2 (depends only on edge_index)
    cudaEventRecord(evFork, 0);
    cudaStreamWaitEvent(s2, evFork, 0);
    k_init_csr<<<nb, 256, 0, s2>>>((const unsigned*)ei, N);
    k_convert<<<eb, 256, 0, s2>>>(ei, E);
    k_scan<<<1, 1024, 0, s2>>>(N);
    k_scatter<<<eb, 256, 0, s2>>>(E);
    cudaEventRecord(evJoin, s2);

    dim3 ggrid((N + 127) / 128, 3);
    int ab = (N * 32 + 255) / 256;

    // GEMM-1 (tf32 tensor cores) runs concurrently with the CSR build
    k_gemm_tf32<<<ggrid, 256, SMEM_GEMM>>>(x, 0, q1w, q1b, k1w, k1b, v1w, v1b, N);

    // join: attention needs both
    cudaStreamWaitEvent(0, evJoin, 0);
    k_attn<<<ab, 256>>>(out, 0, N);

    // layer 2
    k_gemm_tf32<<<ggrid, 256, SMEM_GEMM>>>(x, 1, q2w, q2b, k2w, k2b, v2w, v2b, N);
    k_attn<<<ab, 256>>>(out, 1, N);
}

// round 10
// speedup vs baseline: 1.3982x; 1.3982x over previous
#include <cuda_runtime.h>
#include <math_constants.h>

#define D     128
#define NMAX  50000
#define EMAX  1600000

// ---------------- device scratch (allocation-free, static) ----------------
__device__ int g_is64;
__device__ int g_src[EMAX];
__device__ int g_dst[EMAX];
__device__ __align__(16) int g_deg[NMAX + 4];
__device__ __align__(16) int g_start[NMAX + 4];
__device__ __align__(16) int g_cursor[NMAX + 4];
__device__ int g_csr_src[EMAX];

__device__ __align__(256) float g_Q[(size_t)NMAX * D];        // [N,128]
__device__ __align__(256) float g_KV[(size_t)NMAX * 2 * D];   // [N,256]: K | V interleaved
__device__ __align__(256) float g_H[(size_t)NMAX * D];        // layer-1 output

// ---------------- zero degree histogram + edge width detection (fused) ----
__global__ void k_init_csr(const unsigned* __restrict__ ei, int N) {
    int i = blockIdx.x * blockDim.x + threadIdx.x;
    if (i < N) g_deg[i] = 0;
    if (i == 0) {
        int is64 = 1;
        for (int j = 0; j < 64; j++)
            if (ei[2 * j + 1] != 0u) is64 = 0;
        g_is64 = is64;
    }
}

__global__ void k_convert(const void* __restrict__ ei, int E) {
    int i = blockIdx.x * blockDim.x + threadIdx.x;
    if (i >= E) return;
    int s, d;
    if (g_is64) {
        const long long* p = (const long long*)ei;
        s = (int)p[i];
        d = (int)p[(size_t)E + i];
    } else {
        const int* p = (const int*)ei;
        s = p[i];
        d = p[E + i];
    }
    g_src[i] = s;
    g_dst[i] = d;
    atomicAdd(&g_deg[d], 1);
}

// ---------------- fast single-block exclusive scan ----------------
__global__ void k_scan(int N) {
    __shared__ int warp_sums[32];
    __shared__ int s_carry;
    int tid = threadIdx.x, lane = tid & 31, wid = tid >> 5;
    if (tid == 0) s_carry = 0;
    __syncthreads();

    const int TILE = 4096;
    for (int base = 0; base < N; base += TILE) {
        int idx = base + tid * 4;
        int4 v = make_int4(0, 0, 0, 0);
        if (idx + 3 < N) v = *(const int4*)&g_deg[idx];
        else {
            if (idx + 0 < N) v.x = g_deg[idx + 0];
            if (idx + 1 < N) v.y = g_deg[idx + 1];
            if (idx + 2 < N) v.z = g_deg[idx + 2];
            if (idx + 3 < N) v.w = g_deg[idx + 3];
        }
        int t0 = v.x, t1 = t0 + v.y, t2 = t1 + v.z, t3 = t2 + v.w;
        int inc = t3;
#pragma unroll
        for (int o = 1; o < 32; o <<= 1) {
            int n = __shfl_up_sync(0xFFFFFFFFu, inc, o);
            if (lane >= o) inc += n;
        }
        if (lane == 31) warp_sums[wid] = inc;
        __syncthreads();
        if (wid == 0) {
            int ws = warp_sums[lane];
#pragma unroll
            for (int o = 1; o < 32; o <<= 1) {
                int n = __shfl_up_sync(0xFFFFFFFFu, ws, o);
                if (lane >= o) ws += n;
            }
            warp_sums[lane] = ws;
        }
        __syncthreads();
        int warp_off = wid ? warp_sums[wid - 1] : 0;
        int e0 = s_carry + warp_off + (inc - t3);
        int tile_total = warp_sums[31];

        if (idx + 3 < N) {
            int4 e = make_int4(e0, e0 + t0, e0 + t1, e0 + t2);
            *(int4*)&g_start[idx]  = e;
            *(int4*)&g_cursor[idx] = e;
        } else {
            if (idx + 0 < N) { g_start[idx + 0] = e0;      g_cursor[idx + 0] = e0;      }
            if (idx + 1 < N) { g_start[idx + 1] = e0 + t0; g_cursor[idx + 1] = e0 + t0; }
            if (idx + 2 < N) { g_start[idx + 2] = e0 + t1; g_cursor[idx + 2] = e0 + t1; }
            if (idx + 3 < N) { g_start[idx + 3] = e0 + t2; g_cursor[idx + 3] = e0 + t2; }
        }
        __syncthreads();
        if (tid == 0) s_carry += tile_total;
        __syncthreads();
    }
    if (tid == 0) g_start[N] = s_carry;
}

__global__ void k_scatter(int E) {
    int i = blockIdx.x * blockDim.x + threadIdx.x;
    if (i >= E) return;
    int d = g_dst[i];
    int pos = atomicAdd(&g_cursor[d], 1);
    g_csr_src[pos] = g_src[i];
}

// ---------------- fused QKV GEMM: C = X @ W^T + b ----------------
// 128x128 CTA tile, 256 threads, 8x8 per thread in split blocks.
// k-chunk 32 (4 outer iters, 8 barriers total) — R9 change.
__global__ void __launch_bounds__(256, 2)
k_gemm_qkv(const float* __restrict__ xin, int layer,
           const float* __restrict__ qw, const float* __restrict__ qb,
           const float* __restrict__ kw, const float* __restrict__ kb,
           const float* __restrict__ vw, const float* __restrict__ vb,
           int N) {
    const float* X = layer ? g_H : xin;
    __shared__ float As[32][132];
    __shared__ float Bs[32][132];

    int wsel = blockIdx.y;
    const float* W  = (wsel == 0) ? qw : (wsel == 1) ? kw : vw;
    const float* Bb = (wsel == 0) ? qb : (wsel == 1) ? kb : vb;
    float* C;
    int cs;
    if (wsel == 0)      { C = g_Q;        cs = 128; }
    else if (wsel == 1) { C = g_KV;       cs = 256; }
    else                { C = g_KV + 128; cs = 256; }

    int m0 = blockIdx.x * 128;
    int tid = threadIdx.x;
    int tx = tid & 15, ty = tid >> 4;

    float acc[8][8];
#pragma unroll
    for (int i = 0; i < 8; i++)
#pragma unroll
        for (int j = 0; j < 8; j++) acc[i][j] = 0.0f;

    for (int k0 = 0; k0 < D; k0 += 32) {
        // X tile: 128 rows x 32 k, transposed into As[k][m] (8 float4/thread)
#pragma unroll
        for (int f = tid; f < 1024; f += 256) {
            int r = f >> 3, kq = (f & 7) * 4;
            int gr = m0 + r;
            float4 v = make_float4(0.f, 0.f, 0.f, 0.f);
            if (gr < N) v = *(const float4*)(X + (size_t)gr * D + k0 + kq);
            As[kq + 0][r] = v.x; As[kq + 1][r] = v.y;
            As[kq + 2][r] = v.z; As[kq + 3][r] = v.w;
        }
#pragma unroll
        for (int f = tid; f < 1024; f += 256) {
            int r = f >> 3, kq = (f & 7) * 4;
            float4 v = *(const float4*)(W + (size_t)r * D + k0 + kq);
            Bs[kq + 0][r] = v.x; Bs[kq + 1][r] = v.y;
            Bs[kq + 2][r] = v.z; Bs[kq + 3][r] = v.w;
        }
        __syncthreads();
#pragma unroll
        for (int k = 0; k < 32; k++) {
            float4 a0 = *(const float4*)&As[k][ty * 4];
            float4 a1 = *(const float4*)&As[k][64 + ty * 4];
            float4 b0 = *(const float4*)&Bs[k][tx * 4];
            float4 b1 = *(const float4*)&Bs[k][64 + tx * 4];
            float a[8] = {a0.x, a0.y, a0.z, a0.w, a1.x, a1.y, a1.z, a1.w};
            float b[8] = {b0.x, b0.y, b0.z, b0.w, b1.x, b1.y, b1.z, b1.w};
#pragma unroll
            for (int i = 0; i < 8; i++)
#pragma unroll
                for (int j = 0; j < 8; j++)
                    acc[i][j] += a[i] * b[j];
        }
        __syncthreads();
    }

#pragma unroll
    for (int gi = 0; gi < 2; gi++) {
#pragma unroll
        for (int i = 0; i < 4; i++) {
            int gr = m0 + gi * 64 + ty * 4 + i;
            if (gr >= N) continue;
            int ai = gi * 4 + i;
#pragma unroll
            for (int gj = 0; gj < 2; gj++) {
                int gc = gj * 64 + tx * 4;
                int aj = gj * 4;
                float4 o;
                o.x = acc[ai][aj + 0] + Bb[gc + 0];
                o.y = acc[ai][aj + 1] + Bb[gc + 1];
                o.z = acc[ai][aj + 2] + Bb[gc + 2];
                o.w = acc[ai][aj + 3] + Bb[gc + 3];
                *(float4*)(C + (size_t)gr * cs + gc) = o;
            }
        }
    }
}

// ---------------- fused attention (R5 math; 64-thread blocks) -------------
__global__ void k_attn(float* __restrict__ dout, int layer, int N) {
    int gw = (blockIdx.x * blockDim.x + threadIdx.x) >> 5;
    int lane = threadIdx.x & 31;
    if (gw >= N) return;

    float* outp = layer ? dout : g_H;

    int beg = g_start[gw], end = g_start[gw + 1];
    float4 q = ((const float4*)(g_Q + (size_t)gw * D))[lane];

    float m = -CUDART_INF_F, s = 0.0f;
    float4 acc = make_float4(0.f, 0.f, 0.f, 0.f);

    float4 kf, vf;
    if (beg < end) {
        int sp = g_csr_src[beg];
        const float4* kv = (const float4*)(g_KV + (size_t)sp * 256);
        kf = kv[lane];
        vf = kv[32 + lane];
    }

    for (int e = beg; e < end; e++) {
        float4 kc = kf, vc = vf;
        if (e + 1 < end) {                      // prefetch next edge
            int sp = g_csr_src[e + 1];
            const float4* kv = (const float4*)(g_KV + (size_t)sp * 256);
            kf = kv[lane];
            vf = kv[32 + lane];
        }
        float p = kc.x * q.x + kc.y * q.y + kc.z * q.z + kc.w * q.w;
#pragma unroll
        for (int o = 16; o; o >>= 1) p += __shfl_xor_sync(0xFFFFFFFFu, p, o);
        p *= 0.08838834764831845f;              // 1/sqrt(128)

        float mn = fmaxf(m, p);
        float c  = __expf(m - mn);              // exp(-inf)=0 on first edge
        float ep = __expf(p - mn);
        s = s * c + ep;
        acc.x = acc.x * c + ep * vc.x;
        acc.y = acc.y * c + ep * vc.y;
        acc.z = acc.z * c + ep * vc.z;
        acc.w = acc.w * c + ep * vc.w;
        m = mn;
    }

    float inv = (s > 0.0f) ? 1.0f / s : 0.0f;   // deg==0 -> zeros (matches ref)
    float4 o = make_float4(acc.x * inv, acc.y * inv, acc.z * inv, acc.w * inv);
    if (!layer) {                                // ELU fused into layer-1 epilogue
        o.x = (o.x > 0.f) ? o.x : expm1f(o.x);
        o.y = (o.y > 0.f) ? o.y : expm1f(o.y);
        o.z = (o.z > 0.f) ? o.z : expm1f(o.z);
        o.w = (o.w > 0.f) ? o.w : expm1f(o.w);
    }
    ((float4*)(outp + (size_t)gw * D))[lane] = o;
}

// ---------------- launch: fork CSR build alongside GEMM-1 ----------------
extern "C" void kernel_launch(void* const* d_in, const int* in_sizes, int n_in,
                              void* d_out, int out_size) {
    const float* x   = (const float*)d_in[0];
    const void*  ei  = d_in[1];
    const float* q1w = (const float*)d_in[2];  const float* q1b = (const float*)d_in[3];
    const float* k1w = (const float*)d_in[4];  const float* k1b = (const float*)d_in[5];
    const float* v1w = (const float*)d_in[6];  const float* v1b = (const float*)d_in[7];
    const float* q2w = (const float*)d_in[8];  const float* q2b = (const float*)d_in[9];
    const float* k2w = (const float*)d_in[10]; const float* k2b = (const float*)d_in[11];
    const float* v2w = (const float*)d_in[12]; const float* v2b = (const float*)d_in[13];

    int N = in_sizes[0] / D;
    int E = in_sizes[1] / 2;
    float* out = (float*)d_out;

    int eb = (E + 255) / 256;
    int nb = (N + 255) / 256;

    cudaStream_t s2;
    cudaEvent_t evFork, evJoin;
    cudaStreamCreateWithFlags(&s2, cudaStreamNonBlocking);
    cudaEventCreateWithFlags(&evFork, cudaEventDisableTiming);
    cudaEventCreateWithFlags(&evJoin, cudaEventDisableTiming);

    // fork: CSR build on s2 (depends only on edge_index)
    cudaEventRecord(evFork, 0);
    cudaStreamWaitEvent(s2, evFork, 0);
    k_init_csr<<<nb, 256, 0, s2>>>((const unsigned*)ei, N);
    k_convert<<<eb, 256, 0, s2>>>(ei, E);
    k_scan<<<1, 1024, 0, s2>>>(N);
    k_scatter<<<eb, 256, 0, s2>>>(E);
    cudaEventRecord(evJoin, s2);

    dim3 ggrid((N + 127) / 128, 3);
    int ab = (N * 32 + 63) / 64;     // 64-thread blocks (2 warps) for attn

    // GEMM-1 runs concurrently with the CSR build
    k_gemm_qkv<<<ggrid, 256>>>(x, 0, q1w, q1b, k1w, k1b, v1w, v1b, N);

    // join: attention needs both
    cudaStreamWaitEvent(0, evJoin, 0);
    k_attn<<<ab, 64>>>(out, 0, N);

    // layer 2
    k_gemm_qkv<<<ggrid, 256>>>(x, 1, q2w, q2b, k2w, k2b, v2w, v2b, N);
    k_attn<<<ab, 64>>>(out, 1, N);
}

// round 11
// speedup vs baseline: 1.4584x; 1.0431x over previous
#include <cuda_runtime.h>
#include <cuda_fp16.h>
#include <math_constants.h>

#define D     128
#define NMAX  50000
#define EMAX  1600000

// ---------------- device scratch (allocation-free, static) ----------------
__device__ int g_is64;
__device__ int g_src[EMAX];
__device__ int g_dst[EMAX];
__device__ __align__(16) int g_deg[NMAX + 4];
__device__ __align__(16) int g_start[NMAX + 4];
__device__ __align__(16) int g_cursor[NMAX + 4];
__device__ int g_csr_src[EMAX];

__device__ __align__(256) float  g_Q[(size_t)NMAX * D];      // [N,128] fp32
// fp16 K|V lane-interleaved: row = 32 chunks of 16B; chunk i = {K[4i..4i+3], V[4i..4i+3]}
__device__ __align__(256) __half g_KVh[(size_t)NMAX * 256];  // 512 B/row
__device__ __align__(256) float  g_H[(size_t)NMAX * D];      // layer-1 output

// ---------------- zero degree histogram + edge width detection (fused) ----
__global__ void k_init_csr(const unsigned* __restrict__ ei, int N) {
    int i = blockIdx.x * blockDim.x + threadIdx.x;
    if (i < N) g_deg[i] = 0;
    if (i == 0) {
        int is64 = 1;
        for (int j = 0; j < 64; j++)
            if (ei[2 * j + 1] != 0u) is64 = 0;
        g_is64 = is64;
    }
}

__global__ void k_convert(const void* __restrict__ ei, int E) {
    int i = blockIdx.x * blockDim.x + threadIdx.x;
    if (i >= E) return;
    int s, d;
    if (g_is64) {
        const long long* p = (const long long*)ei;
        s = (int)p[i];
        d = (int)p[(size_t)E + i];
    } else {
        const int* p = (const int*)ei;
        s = p[i];
        d = p[E + i];
    }
    g_src[i] = s;
    g_dst[i] = d;
    atomicAdd(&g_deg[d], 1);
}

// ---------------- fast single-block exclusive scan ----------------
__global__ void k_scan(int N) {
    __shared__ int warp_sums[32];
    __shared__ int s_carry;
    int tid = threadIdx.x, lane = tid & 31, wid = tid >> 5;
    if (tid == 0) s_carry = 0;
    __syncthreads();

    const int TILE = 4096;
    for (int base = 0; base < N; base += TILE) {
        int idx = base + tid * 4;
        int4 v = make_int4(0, 0, 0, 0);
        if (idx + 3 < N) v = *(const int4*)&g_deg[idx];
        else {
            if (idx + 0 < N) v.x = g_deg[idx + 0];
            if (idx + 1 < N) v.y = g_deg[idx + 1];
            if (idx + 2 < N) v.z = g_deg[idx + 2];
            if (idx + 3 < N) v.w = g_deg[idx + 3];
        }
        int t0 = v.x, t1 = t0 + v.y, t2 = t1 + v.z, t3 = t2 + v.w;
        int inc = t3;
#pragma unroll
        for (int o = 1; o < 32; o <<= 1) {
            int n = __shfl_up_sync(0xFFFFFFFFu, inc, o);
            if (lane >= o) inc += n;
        }
        if (lane == 31) warp_sums[wid] = inc;
        __syncthreads();
        if (wid == 0) {
            int ws = warp_sums[lane];
#pragma unroll
            for (int o = 1; o < 32; o <<= 1) {
                int n = __shfl_up_sync(0xFFFFFFFFu, ws, o);
                if (lane >= o) ws += n;
            }
            warp_sums[lane] = ws;
        }
        __syncthreads();
        int warp_off = wid ? warp_sums[wid - 1] : 0;
        int e0 = s_carry + warp_off + (inc - t3);
        int tile_total = warp_sums[31];

        if (idx + 3 < N) {
            int4 e = make_int4(e0, e0 + t0, e0 + t1, e0 + t2);
            *(int4*)&g_start[idx]  = e;
            *(int4*)&g_cursor[idx] = e;
        } else {
            if (idx + 0 < N) { g_start[idx + 0] = e0;      g_cursor[idx + 0] = e0;      }
            if (idx + 1 < N) { g_start[idx + 1] = e0 + t0; g_cursor[idx + 1] = e0 + t0; }
            if (idx + 2 < N) { g_start[idx + 2] = e0 + t1; g_cursor[idx + 2] = e0 + t1; }
            if (idx + 3 < N) { g_start[idx + 3] = e0 + t2; g_cursor[idx + 3] = e0 + t2; }
        }
        __syncthreads();
        if (tid == 0) s_carry += tile_total;
        __syncthreads();
    }
    if (tid == 0) g_start[N] = s_carry;
}

__global__ void k_scatter(int E) {
    int i = blockIdx.x * blockDim.x + threadIdx.x;
    if (i >= E) return;
    int d = g_dst[i];
    int pos = atomicAdd(&g_cursor[d], 1);
    g_csr_src[pos] = g_src[i];
}

// ---------------- fused QKV GEMM: C = X @ W^T + b ----------------
// 128x128 CTA tile, 256 threads, 8x8 per thread (proven R5/R10 kernel).
// wsel 0 -> Q fp32; wsel 1 -> K halves (chunk bytes 0-7); wsel 2 -> V halves (8-15).
__global__ void __launch_bounds__(256, 2)
k_gemm_qkv(const float* __restrict__ xin, int layer,
           const float* __restrict__ qw, const float* __restrict__ qb,
           const float* __restrict__ kw, const float* __restrict__ kb,
           const float* __restrict__ vw, const float* __restrict__ vb,
           int N) {
    const float* X = layer ? g_H : xin;
    __shared__ float As[32][132];
    __shared__ float Bs[32][132];

    int wsel = blockIdx.y;
    const float* W  = (wsel == 0) ? qw : (wsel == 1) ? kw : vw;
    const float* Bb = (wsel == 0) ? qb : (wsel == 1) ? kb : vb;

    int m0 = blockIdx.x * 128;
    int tid = threadIdx.x;
    int tx = tid & 15, ty = tid >> 4;

    float acc[8][8];
#pragma unroll
    for (int i = 0; i < 8; i++)
#pragma unroll
        for (int j = 0; j < 8; j++) acc[i][j] = 0.0f;

    for (int k0 = 0; k0 < D; k0 += 32) {
#pragma unroll
        for (int f = tid; f < 1024; f += 256) {
            int r = f >> 3, kq = (f & 7) * 4;
            int gr = m0 + r;
            float4 v = make_float4(0.f, 0.f, 0.f, 0.f);
            if (gr < N) v = *(const float4*)(X + (size_t)gr * D + k0 + kq);
            As[kq + 0][r] = v.x; As[kq + 1][r] = v.y;
            As[kq + 2][r] = v.z; As[kq + 3][r] = v.w;
        }
#pragma unroll
        for (int f = tid; f < 1024; f += 256) {
            int r = f >> 3, kq = (f & 7) * 4;
            float4 v = *(const float4*)(W + (size_t)r * D + k0 + kq);
            Bs[kq + 0][r] = v.x; Bs[kq + 1][r] = v.y;
            Bs[kq + 2][r] = v.z; Bs[kq + 3][r] = v.w;
        }
        __syncthreads();
#pragma unroll
        for (int k = 0; k < 32; k++) {
            float4 a0 = *(const float4*)&As[k][ty * 4];
            float4 a1 = *(const float4*)&As[k][64 + ty * 4];
            float4 b0 = *(const float4*)&Bs[k][tx * 4];
            float4 b1 = *(const float4*)&Bs[k][64 + tx * 4];
            float a[8] = {a0.x, a0.y, a0.z, a0.w, a1.x, a1.y, a1.z, a1.w};
            float b[8] = {b0.x, b0.y, b0.z, b0.w, b1.x, b1.y, b1.z, b1.w};
#pragma unroll
            for (int i = 0; i < 8; i++)
#pragma unroll
                for (int j = 0; j < 8; j++)
                    acc[i][j] += a[i] * b[j];
        }
        __syncthreads();
    }

#pragma unroll
    for (int gi = 0; gi < 2; gi++) {
#pragma unroll
        for (int i = 0; i < 4; i++) {
            int gr = m0 + gi * 64 + ty * 4 + i;
            if (gr >= N) continue;
            int ai = gi * 4 + i;
#pragma unroll
            for (int gj = 0; gj < 2; gj++) {
                int gc = gj * 64 + tx * 4;      // multiple of 4
                int aj = gj * 4;
                float4 o;
                o.x = acc[ai][aj + 0] + Bb[gc + 0];
                o.y = acc[ai][aj + 1] + Bb[gc + 1];
                o.z = acc[ai][aj + 2] + Bb[gc + 2];
                o.w = acc[ai][aj + 3] + Bb[gc + 3];
                if (wsel == 0) {
                    *(float4*)(g_Q + (size_t)gr * D + gc) = o;
                } else {
                    __half2 h01 = __floats2half2_rn(o.x, o.y);
                    __half2 h23 = __floats2half2_rn(o.z, o.w);
                    uint2 pk;
                    pk.x = *(unsigned*)&h01;
                    pk.y = *(unsigned*)&h23;
                    // chunk (gc>>2): 16 B; K at +0, V at +8
                    char* base = (char*)g_KVh + (size_t)gr * 512
                               + ((gc >> 2) << 4) + (wsel == 2 ? 8 : 0);
                    *(uint2*)base = pk;
                }
            }
        }
    }
}

// ---------------- fused attention: warp per dst node, online softmax ------
// ONE LDG.128 per edge: lane i reads 16 B = {K[4i..4i+3], V[4i..4i+3]} halves.
__global__ void k_attn(float* __restrict__ dout, int layer, int N) {
    int gw = (blockIdx.x * blockDim.x + threadIdx.x) >> 5;
    int lane = threadIdx.x & 31;
    if (gw >= N) return;

    float* outp = layer ? dout : g_H;

    int beg = g_start[gw], end = g_start[gw + 1];
    float4 q = ((const float4*)(g_Q + (size_t)gw * D))[lane];

    float m = -CUDART_INF_F, s = 0.0f;
    float4 acc = make_float4(0.f, 0.f, 0.f, 0.f);

    uint4 kvf;
    if (beg < end)
        kvf = ((const uint4*)((const char*)g_KVh + (size_t)g_csr_src[beg] * 512))[lane];

    for (int e = beg; e < end; e++) {
        uint4 kvc = kvf;
        if (e + 1 < end)                         // prefetch next edge
            kvf = ((const uint4*)((const char*)g_KVh + (size_t)g_csr_src[e + 1] * 512))[lane];

        float2 k01 = __half22float2(*(__half2*)&kvc.x);
        float2 k23 = __half22float2(*(__half2*)&kvc.y);
        float2 v01 = __half22float2(*(__half2*)&kvc.z);
        float2 v23 = __half22float2(*(__half2*)&kvc.w);

        float p = k01.x * q.x + k01.y * q.y + k23.x * q.z + k23.y * q.w;
#pragma unroll
        for (int o = 16; o; o >>= 1) p += __shfl_xor_sync(0xFFFFFFFFu, p, o);
        p *= 0.08838834764831845f;               // 1/sqrt(128)

        float mn = fmaxf(m, p);
        float c  = __expf(m - mn);               // exp(-inf)=0 on first edge
        float ep = __expf(p - mn);
        s = s * c + ep;
        acc.x = acc.x * c + ep * v01.x;
        acc.y = acc.y * c + ep * v01.y;
        acc.z = acc.z * c + ep * v23.x;
        acc.w = acc.w * c + ep * v23.y;
        m = mn;
    }

    float inv = (s > 0.0f) ? 1.0f / s : 0.0f;    // deg==0 -> zeros (matches ref)
    float4 o = make_float4(acc.x * inv, acc.y * inv, acc.z * inv, acc.w * inv);
    if (!layer) {                                 // ELU fused into layer-1 epilogue
        o.x = (o.x > 0.f) ? o.x : expm1f(o.x);
        o.y = (o.y > 0.f) ? o.y : expm1f(o.y);
        o.z = (o.z > 0.f) ? o.z : expm1f(o.z);
        o.w = (o.w > 0.f) ? o.w : expm1f(o.w);
    }
    ((float4*)(outp + (size_t)gw * D))[lane] = o;
}

// ---------------- launch: fork CSR build alongside GEMM-1 ----------------
extern "C" void kernel_launch(void* const* d_in, const int* in_sizes, int n_in,
                              void* d_out, int out_size) {
    const float* x   = (const float*)d_in[0];
    const void*  ei  = d_in[1];
    const float* q1w = (const float*)d_in[2];  const float* q1b = (const float*)d_in[3];
    const float* k1w = (const float*)d_in[4];  const float* k1b = (const float*)d_in[5];
    const float* v1w = (const float*)d_in[6];  const float* v1b = (const float*)d_in[7];
    const float* q2w = (const float*)d_in[8];  const float* q2b = (const float*)d_in[9];
    const float* k2w = (const float*)d_in[10]; const float* k2b = (const float*)d_in[11];
    const float* v2w = (const float*)d_in[12]; const float* v2b = (const float*)d_in[13];

    int N = in_sizes[0] / D;
    int E = in_sizes[1] / 2;
    float* out = (float*)d_out;

    int eb = (E + 255) / 256;
    int nb = (N + 255) / 256;

    cudaStream_t s2;
    cudaEvent_t evFork, evJoin;
    cudaStreamCreateWithFlags(&s2, cudaStreamNonBlocking);
    cudaEventCreateWithFlags(&evFork, cudaEventDisableTiming);
    cudaEventCreateWithFlags(&evJoin, cudaEventDisableTiming);

    // fork: CSR build on s2 (depends only on edge_index)
    cudaEventRecord(evFork, 0);
    cudaStreamWaitEvent(s2, evFork, 0);
    k_init_csr<<<nb, 256, 0, s2>>>((const unsigned*)ei, N);
    k_convert<<<eb, 256, 0, s2>>>(ei, E);
    k_scan<<<1, 1024, 0, s2>>>(N);
    k_scatter<<<eb, 256, 0, s2>>>(E);
    cudaEventRecord(evJoin, s2);

    dim3 ggrid((N + 127) / 128, 3);
    int ab = (N * 32 + 63) / 64;

    // GEMM-1 runs concurrently with the CSR build
    k_gemm_qkv<<<ggrid, 256>>>(x, 0, q1w, q1b, k1w, k1b, v1w, v1b, N);

    // join: attention needs both
    cudaStreamWaitEvent(0, evJoin, 0);
    k_attn<<<ab, 64>>>(out, 0, N);

    // layer 2
    k_gemm_qkv<<<ggrid, 256>>>(x, 1, q2w, q2b, k2w, k2b, v2w, v2b, N);
    k_attn<<<ab, 64>>>(out, 1, N);
}